// round 10
// baseline (speedup 1.0000x reference)
#include <cuda_runtime.h>
#include <cuda_fp16.h>
#include <mma.h>
#include <math.h>
#include <stdint.h>

using namespace nvcuda;

// Problem constants
#define NPTS   32768
#define PPARTS 5
#define MPTS   1024
#define JJ     24
#define HDIM   256
#define NP     (NPTS * PPARTS)   // 163840
#define SMPL_THRESH 0.08f

// Output layout (float32, reference tuple order, concatenated)
#define OFF_TPOSE  0
#define OFF_TDIRS  (NP * 3)
#define OFF_RESD   (2 * NP * 3)
#define OFF_PFLAG  (3 * NP * 3)
#define OFF_INIT   (OFF_PFLAG + NP)
#define OFF_PNORM  (OFF_INIT + NP * 3)

// Scratch (static device arrays — no allocation)
__device__ int   g_nn[NP];
__device__ float g_pnorm[NP];
__device__ float g_init[NP * 3];
__device__ float g_pflag[NP];
// W2^T fp16 image: g_W2h[n*256 + k] = fp16(W2[k][n])
__device__ __half g_W2h[65536];

// ---------------------------------------------------------------------------
// Helpers (sm_80-baseline features only — no tcgen05/TMEM on this toolchain)
// ---------------------------------------------------------------------------
__device__ __forceinline__ uint32_t smem_u32(const void* p) {
    uint32_t a;
    asm("{ .reg .u64 t; cvta.to.shared.u64 t, %1; cvt.u32.u64 %0, t; }" : "=r"(a) : "l"(p));
    return a;
}
__device__ __forceinline__ void cpasync16(uint32_t s, const void* g) {
    asm volatile("cp.async.cg.shared.global [%0], [%1], 16;" :: "r"(s), "l"(g));
}
#define CP_COMMIT() asm volatile("cp.async.commit_group;" ::: "memory")
#define CP_WAIT1()  asm volatile("cp.async.wait_group 1;" ::: "memory")
#define CP_WAIT0()  asm volatile("cp.async.wait_group 0;" ::: "memory")

// ---------------------------------------------------------------------------
// Kernel 0: build fp16 image of W2^T (coalesced writes).
// ---------------------------------------------------------------------------
__global__ void __launch_bounds__(256) prep_w2_kernel(const float* __restrict__ W2)
{
    const int t = blockIdx.x * 256 + threadIdx.x;   // 65536
    const int n = t >> 8;
    const int k = t & 255;
    g_W2h[n * 256 + k] = __float2half_rn(W2[k * 256 + n]);
}

// ---------------------------------------------------------------------------
// Kernel 1: NN search. Block = (512-point chunk, part p). 2 points/thread.
// Candidate arithmetic identical to the R3-passing kernel so argmin matches.
// ---------------------------------------------------------------------------
__global__ void __launch_bounds__(256) nn_kernel(
    const float* __restrict__ pose_pts,
    const float* __restrict__ part_pts,
    float* __restrict__ out)
{
    __shared__ float sx[MPTS], sy[MPTS], sz[MPTS], sq[MPTS];
    const int tid = threadIdx.x;
    const int p   = blockIdx.y;

    for (int i = tid; i < MPTS; i += 256) {
        const float a = part_pts[(p * MPTS + i) * 3 + 0];
        const float b = part_pts[(p * MPTS + i) * 3 + 1];
        const float c = part_pts[(p * MPTS + i) * 3 + 2];
        sx[i] = a; sy[i] = b; sz[i] = c;
        sq[i] = a * a + b * b + c * c;
    }
    __syncthreads();

    const int n0 = blockIdx.x * 512;
    float m2x[2], m2y[2], m2z[2], xn2[2];
    #pragma unroll
    for (int r = 0; r < 2; r++) {
        const int n = n0 + r * 256 + tid;
        const float x = pose_pts[n * 3 + 0];
        const float y = pose_pts[n * 3 + 1];
        const float z = pose_pts[n * 3 + 2];
        m2x[r] = -2.0f * x; m2y[r] = -2.0f * y; m2z[r] = -2.0f * z;
        xn2[r] = x * x + y * y + z * z;
    }

    float best[2] = {3.4e38f, 3.4e38f};
    int   bg[2]   = {0, 0};

    const float4* X4 = (const float4*)sx;
    const float4* Y4 = (const float4*)sy;
    const float4* Z4 = (const float4*)sz;
    const float4* Q4 = (const float4*)sq;

    #pragma unroll 4
    for (int m4 = 0; m4 < MPTS / 4; m4++) {
        const float4 X = X4[m4], Y = Y4[m4], Z = Z4[m4], Q = Q4[m4];
        #pragma unroll
        for (int r = 0; r < 2; r++) {
            const float d0 = fmaxf(fmaf(m2x[r], X.x, xn2[r]) + fmaf(m2y[r], Y.x, fmaf(m2z[r], Z.x, Q.x)), 0.0f);
            const float d1 = fmaxf(fmaf(m2x[r], X.y, xn2[r]) + fmaf(m2y[r], Y.y, fmaf(m2z[r], Z.y, Q.y)), 0.0f);
            const float d2 = fmaxf(fmaf(m2x[r], X.z, xn2[r]) + fmaf(m2y[r], Y.z, fmaf(m2z[r], Z.z, Q.z)), 0.0f);
            const float d3 = fmaxf(fmaf(m2x[r], X.w, xn2[r]) + fmaf(m2y[r], Y.w, fmaf(m2z[r], Z.w, Q.w)), 0.0f);
            const float g = fminf(fminf(d0, d1), fminf(d2, d3));
            if (g < best[r]) { best[r] = g; bg[r] = m4; }
        }
    }

    #pragma unroll
    for (int r = 0; r < 2; r++) {
        const int m4 = bg[r];
        const float4 X = X4[m4], Y = Y4[m4], Z = Z4[m4], Q = Q4[m4];
        const float d0 = fmaxf(fmaf(m2x[r], X.x, xn2[r]) + fmaf(m2y[r], Y.x, fmaf(m2z[r], Z.x, Q.x)), 0.0f);
        const float d1 = fmaxf(fmaf(m2x[r], X.y, xn2[r]) + fmaf(m2y[r], Y.y, fmaf(m2z[r], Z.y, Q.y)), 0.0f);
        const float d2 = fmaxf(fmaf(m2x[r], X.z, xn2[r]) + fmaf(m2y[r], Y.z, fmaf(m2z[r], Z.z, Q.z)), 0.0f);
        int bi = m4 * 4 + 3;                    // first-occurrence within group
        if (d2 == best[r]) bi = m4 * 4 + 2;
        if (d1 == best[r]) bi = m4 * 4 + 1;
        if (d0 == best[r]) bi = m4 * 4 + 0;
        const int n = n0 + r * 256 + tid;
        const int k = n * PPARTS + p;
        g_nn[k] = bi;
        const float pn = sqrtf(best[r]);
        g_pnorm[k] = pn;
        out[OFF_PNORM + k] = pn;
    }
}

// ---------------------------------------------------------------------------
// Kernel 2: blend, 3x3 inverse, rigid transforms. One thread = one (n,p).
// ---------------------------------------------------------------------------
__global__ void __launch_bounds__(256) xform_kernel(
    const float* __restrict__ pose_pts,
    const float* __restrict__ pose_dirs,
    const float* __restrict__ part_pbw,
    const float* __restrict__ Ag,
    const float* __restrict__ bigAg,
    float* __restrict__ out)
{
    __shared__ float sA[JJ * 16];
    __shared__ float sBig[JJ * 16];
    const int tid = threadIdx.x;
    for (int i = tid; i < JJ * 16; i += 256) { sA[i] = Ag[i]; sBig[i] = bigAg[i]; }
    __syncthreads();

    const int k = blockIdx.x * 256 + tid;
    const int n = k / PPARTS;
    const int p = k - n * PPARTS;

    const int nn = g_nn[k];
    const float4* bw4 = (const float4*)(part_pbw + (size_t)(p * MPTS + nn) * JJ);
    float bw[JJ];
    #pragma unroll
    for (int i = 0; i < 6; i++) {
        float4 v = bw4[i];
        bw[4 * i + 0] = v.x; bw[4 * i + 1] = v.y;
        bw[4 * i + 2] = v.z; bw[4 * i + 3] = v.w;
    }

    float Ra[9] = {0,0,0,0,0,0,0,0,0}, ta[3] = {0,0,0};
    float Rb[9] = {0,0,0,0,0,0,0,0,0}, tb[3] = {0,0,0};
    #pragma unroll
    for (int j = 0; j < JJ; j++) {
        const float w = bw[j];
        const float* a = sA   + j * 16;
        const float* b = sBig + j * 16;
        Ra[0]=fmaf(w,a[0],Ra[0]); Ra[1]=fmaf(w,a[1],Ra[1]); Ra[2]=fmaf(w,a[2], Ra[2]); ta[0]=fmaf(w,a[3], ta[0]);
        Ra[3]=fmaf(w,a[4],Ra[3]); Ra[4]=fmaf(w,a[5],Ra[4]); Ra[5]=fmaf(w,a[6], Ra[5]); ta[1]=fmaf(w,a[7], ta[1]);
        Ra[6]=fmaf(w,a[8],Ra[6]); Ra[7]=fmaf(w,a[9],Ra[7]); Ra[8]=fmaf(w,a[10],Ra[8]); ta[2]=fmaf(w,a[11],ta[2]);
        Rb[0]=fmaf(w,b[0],Rb[0]); Rb[1]=fmaf(w,b[1],Rb[1]); Rb[2]=fmaf(w,b[2], Rb[2]); tb[0]=fmaf(w,b[3], tb[0]);
        Rb[3]=fmaf(w,b[4],Rb[3]); Rb[4]=fmaf(w,b[5],Rb[4]); Rb[5]=fmaf(w,b[6], Rb[5]); tb[1]=fmaf(w,b[7], tb[1]);
        Rb[6]=fmaf(w,b[8],Rb[6]); Rb[7]=fmaf(w,b[9],Rb[7]); Rb[8]=fmaf(w,b[10],Rb[8]); tb[2]=fmaf(w,b[11],tb[2]);
    }

    const float i00 = Ra[4]*Ra[8] - Ra[5]*Ra[7];
    const float i01 = Ra[2]*Ra[7] - Ra[1]*Ra[8];
    const float i02 = Ra[1]*Ra[5] - Ra[2]*Ra[4];
    const float i10 = Ra[5]*Ra[6] - Ra[3]*Ra[8];
    const float i11 = Ra[0]*Ra[8] - Ra[2]*Ra[6];
    const float i12 = Ra[2]*Ra[3] - Ra[0]*Ra[5];
    const float i20 = Ra[3]*Ra[7] - Ra[4]*Ra[6];
    const float i21 = Ra[1]*Ra[6] - Ra[0]*Ra[7];
    const float i22 = Ra[0]*Ra[4] - Ra[1]*Ra[3];
    const float det  = Ra[0]*i00 + Ra[1]*i10 + Ra[2]*i20;
    const float rdet = 1.0f / det;

    const float x0 = pose_pts[n * 3 + 0], x1 = pose_pts[n * 3 + 1], x2 = pose_pts[n * 3 + 2];
    const float e0 = pose_dirs[n * 3 + 0], e1 = pose_dirs[n * 3 + 1], e2 = pose_dirs[n * 3 + 2];

    const float vx = x0 - ta[0], vy = x1 - ta[1], vz = x2 - ta[2];
    const float t0 = (i00 * vx + i01 * vy + i02 * vz) * rdet;
    const float t1 = (i10 * vx + i11 * vy + i12 * vz) * rdet;
    const float t2 = (i20 * vx + i21 * vy + i22 * vz) * rdet;

    const float ib0 = Rb[0]*t0 + Rb[1]*t1 + Rb[2]*t2 + tb[0];
    const float ib1 = Rb[3]*t0 + Rb[4]*t1 + Rb[5]*t2 + tb[1];
    const float ib2 = Rb[6]*t0 + Rb[7]*t1 + Rb[8]*t2 + tb[2];

    const float td0 = (i00 * e0 + i01 * e1 + i02 * e2) * rdet;
    const float td1 = (i10 * e0 + i11 * e1 + i12 * e2) * rdet;
    const float td2 = (i20 * e0 + i21 * e1 + i22 * e2) * rdet;

    const float o0 = Rb[0]*td0 + Rb[1]*td1 + Rb[2]*td2;
    const float o1 = Rb[3]*td0 + Rb[4]*td1 + Rb[5]*td2;
    const float o2 = Rb[6]*td0 + Rb[7]*td1 + Rb[8]*td2;

    const float pn   = g_pnorm[k];
    const float flag = (pn < SMPL_THRESH) ? 1.0f : 0.0f;

    g_init[k * 3 + 0] = ib0; g_init[k * 3 + 1] = ib1; g_init[k * 3 + 2] = ib2;
    g_pflag[k] = flag;

    out[OFF_TDIRS + k * 3 + 0] = o0;
    out[OFF_TDIRS + k * 3 + 1] = o1;
    out[OFF_TDIRS + k * 3 + 2] = o2;
    out[OFF_PFLAG + k] = flag;
    out[OFF_INIT + k * 3 + 0] = ib0;
    out[OFF_INIT + k * 3 + 1] = ib1;
    out[OFF_INIT + k * 3 + 2] = ib2;
}

// ---------------------------------------------------------------------------
// Kernel 3: fused MLP via wmma fp16 HMMA, single pass (A and B fp16).
// CTA = 128 rows x 256 cols, 8 warps (4m x 4n, 32x64 warp tiles).
// SMEM 108.5 KB -> 2 CTAs/SM (16 warps). Tables read via __ldg broadcast.
// ---------------------------------------------------------------------------
#define ASTRIDE 264
#define BSTRIDE 40
#define FSTRIDE 136                  /* f32 epilogue stride (128 cols + pad) */
#define SM_A    0                    /* 128 x 264 halves = 67,584 B */
#define SM_B    67584                /* 2 bufs x 20,480 B */
#define SMEM_MLP (SM_B + 2 * 20480)  /* 108,544 B */

__device__ __forceinline__ void load_chunk(uint32_t smbase, int buf, int kc, int tid) {
    const uint32_t dst = smbase + SM_B + (uint32_t)buf * 20480u;
    const int kk = kc * 32;
    #pragma unroll
    for (int it = 0; it < 4; it++) {
        const int i = tid + it * 256;           // 0..1023
        const int n = i >> 2, q = i & 3;
        cpasync16(dst + (uint32_t)(n * 80 + q * 16), g_W2h + n * 256 + kk + q * 8);
    }
}

__global__ void __launch_bounds__(256, 2) mlp_kernel(
    const float* __restrict__ W1, const float* __restrict__ b1,
    const float* __restrict__ b2, const float* __restrict__ W3,
    const float* __restrict__ b3, float* __restrict__ out)
{
    extern __shared__ __align__(16) char sm[];
    __half* aHi = (__half*)(sm + SM_A);

    const int tid = threadIdx.x;
    const int wid = tid >> 5;
    const uint32_t smbase = smem_u32(sm);
    const int k0 = blockIdx.x * 128;

    // start streaming B chunk 0 immediately
    load_chunk(smbase, 0, 0, tid);
    CP_COMMIT();

    // prologue: h1 = relu(x @ W1 + b1) -> fp16 in SMEM (W1/b1 via L1 broadcast)
    {
        const int row = tid >> 1;
        const int c0  = (tid & 1) * 128;
        const float x0 = g_init[(k0 + row) * 3 + 0];
        const float x1 = g_init[(k0 + row) * 3 + 1];
        const float x2 = g_init[(k0 + row) * 3 + 2];
        #pragma unroll 4
        for (int c = c0; c < c0 + 128; c += 2) {
            const float w00 = __ldg(W1 + c),       w01 = __ldg(W1 + c + 1);
            const float w10 = __ldg(W1 + 256 + c), w11 = __ldg(W1 + 256 + c + 1);
            const float w20 = __ldg(W1 + 512 + c), w21 = __ldg(W1 + 512 + c + 1);
            const float h0 = fmaxf(fmaf(x0, w00, fmaf(x1, w10, fmaf(x2, w20, __ldg(b1 + c)))),     0.0f);
            const float h1 = fmaxf(fmaf(x0, w01, fmaf(x1, w11, fmaf(x2, w21, __ldg(b1 + c + 1)))), 0.0f);
            const __half h0h = __float2half_rn(h0);
            const __half h1h = __float2half_rn(h1);
            *(uint32_t*)(aHi + row * ASTRIDE + c) =
                ((uint32_t)__half_as_ushort(h1h) << 16) | __half_as_ushort(h0h);
        }
    }
    __syncthreads();

    const int wm = wid & 3;        // rows wm*32
    const int wn = wid >> 2;       // cols wn*128? no: wn in 0..1 -> see below
    // 8 warps: 4m x 2n would be 32x128 tiles. Use 4m x 2n? We need 2n*128=256.
    // Instead: wm = wid & 3 (4 m-warps, 32 rows each), wn2 = wid >> 2 (2 n-warps,
    // 128 cols each -> 8 frag-cols). C = 2 x 8 frags = 128 regs: too many.
    // -> Use 2m x 4n: 64x64 tiles, C = 4x4 = 128 regs: too many for 2 CTAs.
    // -> Final: 4m x 4n requires 16 warps. With 8 warps choose 4m x 2n with
    //    C 2x8? No. Choose 32x64 tiles over a 2-step n loop: each warp covers
    //    cols (wid>>2)*64 in two halves? Simplest: 4m x 2n with per-warp n-loop
    //    of 2 iterations sharing A frags, C[2][4] per iteration accumulated in
    //    a C[2][8] array = 16 frags = 128 regs. Too many.
    // Resolution: keep 8 warps as 2m x 4n (64x64) but C in 2 half-passes is
    // impossible (K accumulation). So: accept C[2][4] with 32x64 tiles and a
    // 4m x 4n grid needs 16 warps -> run 8 warps with wm covering 2 row-blocks
    // sequentially is also K-blocked. Therefore: 8 warps, 4m x 2n, warp tile
    // 32x128 with C[2][8] = 16 frags is the only full-coverage option at 64
    // accum regs... C[2][8] = 16 frags x 8 f32 = 128 regs. No.
    //
    // Chosen layout: 8 warps as 4m x 2n, warp tile 32 x 128, but with fp16
    // accumulators? No - precision. FINAL: 2m x 4n (64x64), C[4][4]=128 regs,
    // 1 CTA... defeats the purpose.
    //
    // Actual resolution used below: 256 threads = 8 warps arranged 4m x 2n,
    // tile 32x128, C[2][8] but accumulate in fp32 fragments 16x8... we instead
    // split N: each warp handles cols wn*128 .. +127 as 8 nj frags with C
    // stored as 16 fragments of 8 regs = 128 regs. Register-heavy but
    // launch_bounds(256,2) forces spill of addressing only; accumulators are
    // live throughout. To stay under 128 total regs we reduce to warp tile
    // 32x64 and run the n-dimension twice with separate k-loops is invalid.
    //
    // => Pragmatic final: 32x64 tiles, 4m x 4n over 16 logical warp-slots,
    // each physical warp owns TWO m-slots (rows wm*32 and wm*32+... no.
    (void)wn;

    // ---- FINAL simple layout: 8 warps, 2m x 4n, 64x64 tiles, C[4][4]. ----
    const int wm2 = wid & 1;
    const int wn4 = wid >> 1;

    wmma::fragment<wmma::accumulator, 16, 16, 16, float> C[4][4];
    #pragma unroll
    for (int mt = 0; mt < 4; mt++)
        #pragma unroll
        for (int nj = 0; nj < 4; nj++) wmma::fill_fragment(C[mt][nj], 0.0f);

    for (int kc = 0; kc < 8; kc++) {
        if (kc < 7) {
            load_chunk(smbase, (kc + 1) & 1, kc + 1, tid);
            CP_COMMIT();
            CP_WAIT1();
        } else {
            CP_WAIT0();
        }
        __syncthreads();

        const __half* bHi = (const __half*)(sm + SM_B + (kc & 1) * 20480);

        #pragma unroll
        for (int kt = 0; kt < 2; kt++) {
            const int kg = kc * 32 + kt * 16;
            wmma::fragment<wmma::matrix_a, 16, 16, 16, __half, wmma::row_major> Ah[4];
            #pragma unroll
            for (int mt = 0; mt < 4; mt++)
                wmma::load_matrix_sync(Ah[mt], aHi + (wm2 * 64 + mt * 16) * ASTRIDE + kg, ASTRIDE);
            #pragma unroll
            for (int nj = 0; nj < 4; nj++) {
                wmma::fragment<wmma::matrix_b, 16, 16, 16, __half, wmma::col_major> B;
                wmma::load_matrix_sync(B, bHi + (wn4 * 64 + nj * 16) * BSTRIDE + kt * 16, BSTRIDE);
                #pragma unroll
                for (int mt = 0; mt < 4; mt++) wmma::mma_sync(C[mt][nj], Ah[mt], B, C[mt][nj]);
            }
        }
        __syncthreads();
    }

    // epilogue in two column-half passes (f32 C tile doesn't fit SMEM whole)
    float* sF = (float*)sm;
    float p0 = 0.0f, p1 = 0.0f, p2 = 0.0f;
    const int row = tid >> 1;
    const int cl0 = (tid & 1) * 64;

    #pragma unroll
    for (int half = 0; half < 2; half++) {
        if ((wn4 >> 1) == half) {
            #pragma unroll
            for (int mt = 0; mt < 4; mt++)
                #pragma unroll
                for (int nj = 0; nj < 4; nj++)
                    wmma::store_matrix_sync(
                        sF + (wm2 * 64 + mt * 16) * FSTRIDE + (wn4 & 1) * 64 + nj * 16,
                        C[mt][nj], FSTRIDE, wmma::mem_row_major);
        }
        __syncthreads();
        #pragma unroll 4
        for (int c = cl0; c < cl0 + 64; c++) {
            const int gc = half * 128 + c;
            const float h = fmaxf(sF[row * FSTRIDE + c] + __ldg(b2 + gc), 0.0f);
            p0 = fmaf(h, __ldg(W3 + gc * 3 + 0), p0);
            p1 = fmaf(h, __ldg(W3 + gc * 3 + 1), p1);
            p2 = fmaf(h, __ldg(W3 + gc * 3 + 2), p2);
        }
        __syncthreads();
    }

    p0 += __shfl_xor_sync(0xffffffffu, p0, 1);
    p1 += __shfl_xor_sync(0xffffffffu, p1, 1);
    p2 += __shfl_xor_sync(0xffffffffu, p2, 1);
    if ((tid & 1) == 0) {
        const int k = k0 + row;
        const float fl = g_pflag[k];
        const float r0 = 0.05f * tanhf(p0 + __ldg(b3 + 0)) * fl;
        const float r1 = 0.05f * tanhf(p1 + __ldg(b3 + 1)) * fl;
        const float r2 = 0.05f * tanhf(p2 + __ldg(b3 + 2)) * fl;
        out[OFF_RESD + k * 3 + 0] = r0;
        out[OFF_RESD + k * 3 + 1] = r1;
        out[OFF_RESD + k * 3 + 2] = r2;
        out[OFF_TPOSE + k * 3 + 0] = g_init[k * 3 + 0] + r0;
        out[OFF_TPOSE + k * 3 + 1] = g_init[k * 3 + 1] + r1;
        out[OFF_TPOSE + k * 3 + 2] = g_init[k * 3 + 2] + r2;
    }
}

// ---------------------------------------------------------------------------
extern "C" void kernel_launch(void* const* d_in, const int* in_sizes, int n_in,
                              void* d_out, int out_size)
{
    const float* pose_pts  = (const float*)d_in[0];
    const float* pose_dirs = (const float*)d_in[1];
    const float* part_pts  = (const float*)d_in[2];
    const float* part_pbw  = (const float*)d_in[3];
    const float* A         = (const float*)d_in[4];
    const float* bigA      = (const float*)d_in[5];
    const float* W1        = (const float*)d_in[6];
    const float* b1        = (const float*)d_in[7];
    const float* W2        = (const float*)d_in[8];
    const float* b2        = (const float*)d_in[9];
    const float* W3        = (const float*)d_in[10];
    const float* b3        = (const float*)d_in[11];
    // d_in[12] = lengths2: always == M for this shape

    float* out = (float*)d_out;

    cudaFuncSetAttribute(mlp_kernel, cudaFuncAttributeMaxDynamicSharedMemorySize, SMEM_MLP);

    prep_w2_kernel<<<256, 256>>>(W2);
    nn_kernel<<<dim3(NPTS / 512, PPARTS), 256>>>(pose_pts, part_pts, out);
    xform_kernel<<<NP / 256, 256>>>(pose_pts, pose_dirs, part_pbw, A, bigA, out);
    mlp_kernel<<<NP / 128, 256, SMEM_MLP>>>(W1, b1, b2, W3, b3, out);
}

// round 16
// speedup vs baseline: 1.5676x; 1.5676x over previous
#include <cuda_runtime.h>
#include <cuda_fp16.h>
#include <mma.h>
#include <math.h>
#include <stdint.h>

using namespace nvcuda;

// Problem constants
#define NPTS   32768
#define PPARTS 5
#define MPTS   1024
#define JJ     24
#define HDIM   256
#define NP     (NPTS * PPARTS)   // 163840
#define SMPL_THRESH 0.08f

// Output layout (float32, reference tuple order, concatenated)
#define OFF_TPOSE  0
#define OFF_TDIRS  (NP * 3)
#define OFF_RESD   (2 * NP * 3)
#define OFF_PFLAG  (3 * NP * 3)
#define OFF_INIT   (OFF_PFLAG + NP)
#define OFF_PNORM  (OFF_INIT + NP * 3)

// Scratch (static device arrays — no allocation)
__device__ int   g_nn[NP];
__device__ float g_pnorm[NP];
__device__ float g_init[NP * 3];
__device__ float g_pflag[NP];
// W2^T fp16 image: g_W2h[n*256 + k] = fp16(W2[k][n])
__device__ __half g_W2h[65536];

// ---------------------------------------------------------------------------
// Helpers (sm_80-baseline features only — no tcgen05/TMEM on this toolchain)
// ---------------------------------------------------------------------------
__device__ __forceinline__ uint32_t smem_u32(const void* p) {
    uint32_t a;
    asm("{ .reg .u64 t; cvta.to.shared.u64 t, %1; cvt.u32.u64 %0, t; }" : "=r"(a) : "l"(p));
    return a;
}
__device__ __forceinline__ void cpasync16(uint32_t s, const void* g) {
    asm volatile("cp.async.cg.shared.global [%0], [%1], 16;" :: "r"(s), "l"(g));
}
#define CP_COMMIT() asm volatile("cp.async.commit_group;" ::: "memory")
#define CP_WAIT1()  asm volatile("cp.async.wait_group 1;" ::: "memory")
#define CP_WAIT0()  asm volatile("cp.async.wait_group 0;" ::: "memory")

// ---------------------------------------------------------------------------
// Kernel 0: build fp16 image of W2^T (coalesced writes).
// ---------------------------------------------------------------------------
__global__ void __launch_bounds__(256) prep_w2_kernel(const float* __restrict__ W2)
{
    const int t = blockIdx.x * 256 + threadIdx.x;   // 65536
    const int n = t >> 8;
    const int k = t & 255;
    g_W2h[n * 256 + k] = __float2half_rn(W2[k * 256 + n]);
}

// ---------------------------------------------------------------------------
// Kernel 1: NN search. Block = (512-point chunk, part p). 2 points/thread.
// Candidate arithmetic identical to the R3-passing kernel so argmin matches.
// ---------------------------------------------------------------------------
__global__ void __launch_bounds__(256) nn_kernel(
    const float* __restrict__ pose_pts,
    const float* __restrict__ part_pts,
    float* __restrict__ out)
{
    __shared__ float sx[MPTS], sy[MPTS], sz[MPTS], sq[MPTS];
    const int tid = threadIdx.x;
    const int p   = blockIdx.y;

    for (int i = tid; i < MPTS; i += 256) {
        const float a = part_pts[(p * MPTS + i) * 3 + 0];
        const float b = part_pts[(p * MPTS + i) * 3 + 1];
        const float c = part_pts[(p * MPTS + i) * 3 + 2];
        sx[i] = a; sy[i] = b; sz[i] = c;
        sq[i] = a * a + b * b + c * c;
    }
    __syncthreads();

    const int n0 = blockIdx.x * 512;
    float m2x[2], m2y[2], m2z[2], xn2[2];
    #pragma unroll
    for (int r = 0; r < 2; r++) {
        const int n = n0 + r * 256 + tid;
        const float x = pose_pts[n * 3 + 0];
        const float y = pose_pts[n * 3 + 1];
        const float z = pose_pts[n * 3 + 2];
        m2x[r] = -2.0f * x; m2y[r] = -2.0f * y; m2z[r] = -2.0f * z;
        xn2[r] = x * x + y * y + z * z;
    }

    float best[2] = {3.4e38f, 3.4e38f};
    int   bg[2]   = {0, 0};

    const float4* X4 = (const float4*)sx;
    const float4* Y4 = (const float4*)sy;
    const float4* Z4 = (const float4*)sz;
    const float4* Q4 = (const float4*)sq;

    #pragma unroll 4
    for (int m4 = 0; m4 < MPTS / 4; m4++) {
        const float4 X = X4[m4], Y = Y4[m4], Z = Z4[m4], Q = Q4[m4];
        #pragma unroll
        for (int r = 0; r < 2; r++) {
            const float d0 = fmaxf(fmaf(m2x[r], X.x, xn2[r]) + fmaf(m2y[r], Y.x, fmaf(m2z[r], Z.x, Q.x)), 0.0f);
            const float d1 = fmaxf(fmaf(m2x[r], X.y, xn2[r]) + fmaf(m2y[r], Y.y, fmaf(m2z[r], Z.y, Q.y)), 0.0f);
            const float d2 = fmaxf(fmaf(m2x[r], X.z, xn2[r]) + fmaf(m2y[r], Y.z, fmaf(m2z[r], Z.z, Q.z)), 0.0f);
            const float d3 = fmaxf(fmaf(m2x[r], X.w, xn2[r]) + fmaf(m2y[r], Y.w, fmaf(m2z[r], Z.w, Q.w)), 0.0f);
            const float g = fminf(fminf(d0, d1), fminf(d2, d3));
            if (g < best[r]) { best[r] = g; bg[r] = m4; }
        }
    }

    #pragma unroll
    for (int r = 0; r < 2; r++) {
        const int m4 = bg[r];
        const float4 X = X4[m4], Y = Y4[m4], Z = Z4[m4], Q = Q4[m4];
        const float d0 = fmaxf(fmaf(m2x[r], X.x, xn2[r]) + fmaf(m2y[r], Y.x, fmaf(m2z[r], Z.x, Q.x)), 0.0f);
        const float d1 = fmaxf(fmaf(m2x[r], X.y, xn2[r]) + fmaf(m2y[r], Y.y, fmaf(m2z[r], Z.y, Q.y)), 0.0f);
        const float d2 = fmaxf(fmaf(m2x[r], X.z, xn2[r]) + fmaf(m2y[r], Y.z, fmaf(m2z[r], Z.z, Q.z)), 0.0f);
        int bi = m4 * 4 + 3;                    // first-occurrence within group
        if (d2 == best[r]) bi = m4 * 4 + 2;
        if (d1 == best[r]) bi = m4 * 4 + 1;
        if (d0 == best[r]) bi = m4 * 4 + 0;
        const int n = n0 + r * 256 + tid;
        const int k = n * PPARTS + p;
        g_nn[k] = bi;
        const float pn = sqrtf(best[r]);
        g_pnorm[k] = pn;
        out[OFF_PNORM + k] = pn;
    }
}

// ---------------------------------------------------------------------------
// Kernel 2: blend, 3x3 inverse, rigid transforms. One thread = one (n,p).
// ---------------------------------------------------------------------------
__global__ void __launch_bounds__(256) xform_kernel(
    const float* __restrict__ pose_pts,
    const float* __restrict__ pose_dirs,
    const float* __restrict__ part_pbw,
    const float* __restrict__ Ag,
    const float* __restrict__ bigAg,
    float* __restrict__ out)
{
    __shared__ float sA[JJ * 16];
    __shared__ float sBig[JJ * 16];
    const int tid = threadIdx.x;
    for (int i = tid; i < JJ * 16; i += 256) { sA[i] = Ag[i]; sBig[i] = bigAg[i]; }
    __syncthreads();

    const int k = blockIdx.x * 256 + tid;
    const int n = k / PPARTS;
    const int p = k - n * PPARTS;

    const int nn = g_nn[k];
    const float4* bw4 = (const float4*)(part_pbw + (size_t)(p * MPTS + nn) * JJ);
    float bw[JJ];
    #pragma unroll
    for (int i = 0; i < 6; i++) {
        float4 v = bw4[i];
        bw[4 * i + 0] = v.x; bw[4 * i + 1] = v.y;
        bw[4 * i + 2] = v.z; bw[4 * i + 3] = v.w;
    }

    float Ra[9] = {0,0,0,0,0,0,0,0,0}, ta[3] = {0,0,0};
    float Rb[9] = {0,0,0,0,0,0,0,0,0}, tb[3] = {0,0,0};
    #pragma unroll
    for (int j = 0; j < JJ; j++) {
        const float w = bw[j];
        const float* a = sA   + j * 16;
        const float* b = sBig + j * 16;
        Ra[0]=fmaf(w,a[0],Ra[0]); Ra[1]=fmaf(w,a[1],Ra[1]); Ra[2]=fmaf(w,a[2], Ra[2]); ta[0]=fmaf(w,a[3], ta[0]);
        Ra[3]=fmaf(w,a[4],Ra[3]); Ra[4]=fmaf(w,a[5],Ra[4]); Ra[5]=fmaf(w,a[6], Ra[5]); ta[1]=fmaf(w,a[7], ta[1]);
        Ra[6]=fmaf(w,a[8],Ra[6]); Ra[7]=fmaf(w,a[9],Ra[7]); Ra[8]=fmaf(w,a[10],Ra[8]); ta[2]=fmaf(w,a[11],ta[2]);
        Rb[0]=fmaf(w,b[0],Rb[0]); Rb[1]=fmaf(w,b[1],Rb[1]); Rb[2]=fmaf(w,b[2], Rb[2]); tb[0]=fmaf(w,b[3], tb[0]);
        Rb[3]=fmaf(w,b[4],Rb[3]); Rb[4]=fmaf(w,b[5],Rb[4]); Rb[5]=fmaf(w,b[6], Rb[5]); tb[1]=fmaf(w,b[7], tb[1]);
        Rb[6]=fmaf(w,b[8],Rb[6]); Rb[7]=fmaf(w,b[9],Rb[7]); Rb[8]=fmaf(w,b[10],Rb[8]); tb[2]=fmaf(w,b[11],tb[2]);
    }

    const float i00 = Ra[4]*Ra[8] - Ra[5]*Ra[7];
    const float i01 = Ra[2]*Ra[7] - Ra[1]*Ra[8];
    const float i02 = Ra[1]*Ra[5] - Ra[2]*Ra[4];
    const float i10 = Ra[5]*Ra[6] - Ra[3]*Ra[8];
    const float i11 = Ra[0]*Ra[8] - Ra[2]*Ra[6];
    const float i12 = Ra[2]*Ra[3] - Ra[0]*Ra[5];
    const float i20 = Ra[3]*Ra[7] - Ra[4]*Ra[6];
    const float i21 = Ra[1]*Ra[6] - Ra[0]*Ra[7];
    const float i22 = Ra[0]*Ra[4] - Ra[1]*Ra[3];
    const float det  = Ra[0]*i00 + Ra[1]*i10 + Ra[2]*i20;
    const float rdet = 1.0f / det;

    const float x0 = pose_pts[n * 3 + 0], x1 = pose_pts[n * 3 + 1], x2 = pose_pts[n * 3 + 2];
    const float e0 = pose_dirs[n * 3 + 0], e1 = pose_dirs[n * 3 + 1], e2 = pose_dirs[n * 3 + 2];

    const float vx = x0 - ta[0], vy = x1 - ta[1], vz = x2 - ta[2];
    const float t0 = (i00 * vx + i01 * vy + i02 * vz) * rdet;
    const float t1 = (i10 * vx + i11 * vy + i12 * vz) * rdet;
    const float t2 = (i20 * vx + i21 * vy + i22 * vz) * rdet;

    const float ib0 = Rb[0]*t0 + Rb[1]*t1 + Rb[2]*t2 + tb[0];
    const float ib1 = Rb[3]*t0 + Rb[4]*t1 + Rb[5]*t2 + tb[1];
    const float ib2 = Rb[6]*t0 + Rb[7]*t1 + Rb[8]*t2 + tb[2];

    const float td0 = (i00 * e0 + i01 * e1 + i02 * e2) * rdet;
    const float td1 = (i10 * e0 + i11 * e1 + i12 * e2) * rdet;
    const float td2 = (i20 * e0 + i21 * e1 + i22 * e2) * rdet;

    const float o0 = Rb[0]*td0 + Rb[1]*td1 + Rb[2]*td2;
    const float o1 = Rb[3]*td0 + Rb[4]*td1 + Rb[5]*td2;
    const float o2 = Rb[6]*td0 + Rb[7]*td1 + Rb[8]*td2;

    const float pn   = g_pnorm[k];
    const float flag = (pn < SMPL_THRESH) ? 1.0f : 0.0f;

    g_init[k * 3 + 0] = ib0; g_init[k * 3 + 1] = ib1; g_init[k * 3 + 2] = ib2;
    g_pflag[k] = flag;

    out[OFF_TDIRS + k * 3 + 0] = o0;
    out[OFF_TDIRS + k * 3 + 1] = o1;
    out[OFF_TDIRS + k * 3 + 2] = o2;
    out[OFF_PFLAG + k] = flag;
    out[OFF_INIT + k * 3 + 0] = ib0;
    out[OFF_INIT + k * 3 + 1] = ib1;
    out[OFF_INIT + k * 3 + 2] = ib2;
}

// ---------------------------------------------------------------------------
// Kernel 3: fused MLP via wmma fp16 HMMA, single pass (fp16 A and B).
// CTA = 128 rows x 256 cols, 8 warps (2m x 4n, 64x64 tiles).
// Epilogue f32 stage: FSTRIDE must be >= 256 (full column count) — 260.
// ---------------------------------------------------------------------------
#define ASTRIDE 264
#define BSTRIDE 40
#define FSTRIDE 260                  /* f32 epilogue stride, >= 256 cols */
#define SM_A    0                    /* 128 x 264 halves = 67,584 B */
#define SM_B    67584                /* 2 bufs x 20,480 B */
#define SM_TAB  108544               /* W1 768 | b1 256 floats */
#define SMEM_MLP 133120              /* >= (127*260+256)*4 = 133,104 B */

__device__ __forceinline__ void load_chunk(uint32_t smbase, int buf, int kc, int tid) {
    const uint32_t dst = smbase + SM_B + (uint32_t)buf * 20480u;
    const int kk = kc * 32;
    #pragma unroll
    for (int it = 0; it < 4; it++) {
        const int i = tid + it * 256;           // 0..1023
        const int n = i >> 2, q = i & 3;
        cpasync16(dst + (uint32_t)(n * 80 + q * 16), g_W2h + n * 256 + kk + q * 8);
    }
}

__global__ void __launch_bounds__(256, 1) mlp_kernel(
    const float* __restrict__ W1, const float* __restrict__ b1,
    const float* __restrict__ b2, const float* __restrict__ W3,
    const float* __restrict__ b3, float* __restrict__ out)
{
    extern __shared__ __align__(16) char sm[];
    __half* aHi = (__half*)(sm + SM_A);
    float* tab = (float*)(sm + SM_TAB);
    float* sW1 = tab;
    float* sb1 = tab + 768;

    const int tid = threadIdx.x;
    const int wid = tid >> 5;
    const uint32_t smbase = smem_u32(sm);
    const int k0 = blockIdx.x * 128;

    // start streaming B chunk 0 immediately
    load_chunk(smbase, 0, 0, tid);
    CP_COMMIT();

    // stage tables
    for (int i = tid; i < 768; i += 256) sW1[i] = W1[i];
    sb1[tid] = b1[tid];
    __syncthreads();

    // prologue: h1 = relu(x @ W1 + b1) -> fp16 in SMEM
    {
        const int row = tid >> 1;
        const int c0  = (tid & 1) * 128;
        const float x0 = g_init[(k0 + row) * 3 + 0];
        const float x1 = g_init[(k0 + row) * 3 + 1];
        const float x2 = g_init[(k0 + row) * 3 + 2];
        #pragma unroll 4
        for (int c = c0; c < c0 + 128; c += 2) {
            const float h0 = fmaxf(fmaf(x0, sW1[c],     fmaf(x1, sW1[256 + c],     fmaf(x2, sW1[512 + c],     sb1[c]))),     0.0f);
            const float h1 = fmaxf(fmaf(x0, sW1[c + 1], fmaf(x1, sW1[256 + c + 1], fmaf(x2, sW1[512 + c + 1], sb1[c + 1]))), 0.0f);
            const __half h0h = __float2half_rn(h0);
            const __half h1h = __float2half_rn(h1);
            *(uint32_t*)(aHi + row * ASTRIDE + c) =
                ((uint32_t)__half_as_ushort(h1h) << 16) | __half_as_ushort(h0h);
        }
    }
    __syncthreads();

    const int wm = wid & 1;        // rows wm*64
    const int wn = wid >> 1;       // cols wn*64

    wmma::fragment<wmma::accumulator, 16, 16, 16, float> C[4][4];
    #pragma unroll
    for (int mt = 0; mt < 4; mt++)
        #pragma unroll
        for (int nj = 0; nj < 4; nj++) wmma::fill_fragment(C[mt][nj], 0.0f);

    for (int kc = 0; kc < 8; kc++) {
        if (kc < 7) {
            load_chunk(smbase, (kc + 1) & 1, kc + 1, tid);
            CP_COMMIT();
            CP_WAIT1();
        } else {
            CP_WAIT0();
        }
        __syncthreads();

        const __half* bHi = (const __half*)(sm + SM_B + (kc & 1) * 20480);

        #pragma unroll
        for (int kt = 0; kt < 2; kt++) {
            const int kg = kc * 32 + kt * 16;
            wmma::fragment<wmma::matrix_a, 16, 16, 16, __half, wmma::row_major> Ah[4];
            #pragma unroll
            for (int mt = 0; mt < 4; mt++)
                wmma::load_matrix_sync(Ah[mt], aHi + (wm * 64 + mt * 16) * ASTRIDE + kg, ASTRIDE);
            #pragma unroll
            for (int nj = 0; nj < 4; nj++) {
                wmma::fragment<wmma::matrix_b, 16, 16, 16, __half, wmma::col_major> B;
                wmma::load_matrix_sync(B, bHi + (wn * 64 + nj * 16) * BSTRIDE + kt * 16, BSTRIDE);
                #pragma unroll
                for (int mt = 0; mt < 4; mt++) wmma::mma_sync(C[mt][nj], Ah[mt], B, C[mt][nj]);
            }
        }
        __syncthreads();
    }

    // epilogue: accum -> SMEM f32 (reuses whole smem block), stride 260 >= 256
    float* sF = (float*)sm;
    #pragma unroll
    for (int mt = 0; mt < 4; mt++)
        #pragma unroll
        for (int nj = 0; nj < 4; nj++)
            wmma::store_matrix_sync(sF + (wm * 64 + mt * 16) * FSTRIDE + wn * 64 + nj * 16,
                                    C[mt][nj], FSTRIDE, wmma::mem_row_major);
    __syncthreads();

    {
        const int row = tid >> 1;
        const int c0  = (tid & 1) * 128;
        float p0 = 0.0f, p1 = 0.0f, p2 = 0.0f;
        #pragma unroll 4
        for (int c = c0; c < c0 + 128; c++) {
            const float h = fmaxf(sF[row * FSTRIDE + c] + __ldg(b2 + c), 0.0f);
            p0 = fmaf(h, __ldg(W3 + c * 3 + 0), p0);
            p1 = fmaf(h, __ldg(W3 + c * 3 + 1), p1);
            p2 = fmaf(h, __ldg(W3 + c * 3 + 2), p2);
        }
        p0 += __shfl_xor_sync(0xffffffffu, p0, 1);
        p1 += __shfl_xor_sync(0xffffffffu, p1, 1);
        p2 += __shfl_xor_sync(0xffffffffu, p2, 1);
        if ((tid & 1) == 0) {
            const int k = k0 + row;
            const float fl = g_pflag[k];
            const float r0 = 0.05f * tanhf(p0 + __ldg(b3 + 0)) * fl;
            const float r1 = 0.05f * tanhf(p1 + __ldg(b3 + 1)) * fl;
            const float r2 = 0.05f * tanhf(p2 + __ldg(b3 + 2)) * fl;
            out[OFF_RESD + k * 3 + 0] = r0;
            out[OFF_RESD + k * 3 + 1] = r1;
            out[OFF_RESD + k * 3 + 2] = r2;
            out[OFF_TPOSE + k * 3 + 0] = g_init[k * 3 + 0] + r0;
            out[OFF_TPOSE + k * 3 + 1] = g_init[k * 3 + 1] + r1;
            out[OFF_TPOSE + k * 3 + 2] = g_init[k * 3 + 2] + r2;
        }
    }
}

// ---------------------------------------------------------------------------
extern "C" void kernel_launch(void* const* d_in, const int* in_sizes, int n_in,
                              void* d_out, int out_size)
{
    const float* pose_pts  = (const float*)d_in[0];
    const float* pose_dirs = (const float*)d_in[1];
    const float* part_pts  = (const float*)d_in[2];
    const float* part_pbw  = (const float*)d_in[3];
    const float* A         = (const float*)d_in[4];
    const float* bigA      = (const float*)d_in[5];
    const float* W1        = (const float*)d_in[6];
    const float* b1        = (const float*)d_in[7];
    const float* W2        = (const float*)d_in[8];
    const float* b2        = (const float*)d_in[9];
    const float* W3        = (const float*)d_in[10];
    const float* b3        = (const float*)d_in[11];
    // d_in[12] = lengths2: always == M for this shape

    float* out = (float*)d_out;

    cudaFuncSetAttribute(mlp_kernel, cudaFuncAttributeMaxDynamicSharedMemorySize, SMEM_MLP);

    prep_w2_kernel<<<256, 256>>>(W2);
    nn_kernel<<<dim3(NPTS / 512, PPARTS), 256>>>(pose_pts, part_pts, out);
    xform_kernel<<<NP / 256, 256>>>(pose_pts, pose_dirs, part_pbw, A, bigA, out);
    mlp_kernel<<<NP / 128, 256, SMEM_MLP>>>(W1, b1, b2, W3, b3, out);
}